// round 3
// baseline (speedup 1.0000x reference)
#include <cuda_runtime.h>
#include <math.h>

#define NC 19
#define ND 256
#define NB 8
#define HW 16384              // 128*128
#define NPIX (NB*HW)          // 131072
#define NCHUNK 4
#define DCH (ND/NCHUNK)       // 64
#define EPS 1e-8f
#define P1TILE 512            // pixels per pass1 block
#define P2TILE 512            // pixels per pass2 block

// ---------------- static scratch ----------------
__device__ float g_S[NC*ND];          // class sums
__device__ float g_counts[NC];
__device__ float g_centers[NC*ND];
__device__ float g_ncen[NC];
__device__ float g_dotp[NCHUNK*NPIX]; // per-pixel partial dot(feat, center)
__device__ float g_nsqp[NCHUNK*NPIX]; // per-pixel partial ||feat||^2
__device__ float g_percls[NC];
__device__ float g_diff;

// ---------------- kernel 0: zero accumulators ----------------
__global__ void k_zero() {
    int i = blockIdx.x * blockDim.x + threadIdx.x;
    if (i < NC*ND) g_S[i] = 0.f;
    if (i < NC) { g_counts[i] = 0.f; g_percls[i] = 0.f; }
}

// ---------------- kernel 0b: label histogram (counts) ----------------
__global__ __launch_bounds__(256) void k_count(const int4* __restrict__ T) {
    __shared__ int h[20];
    const int tid = threadIdx.x;
    if (tid < 20) h[tid] = 0;
    __syncthreads();
    // 32 blocks x 256 threads x 4 int4 = 131072 labels
    const int base = blockIdx.x * 1024 + tid;
    #pragma unroll
    for (int i = 0; i < 4; i++) {
        int4 l = T[base + i*256];
        atomicAdd(&h[l.x], 1); atomicAdd(&h[l.y], 1);
        atomicAdd(&h[l.z], 1); atomicAdd(&h[l.w], 1);
    }
    __syncthreads();
    if (tid < NC) atomicAdd(&g_counts[tid], (float)h[tid]);
}

// ---------------- kernel 1: class sums, transposed scatter ----------------
// block = (b, 512-pixel tile); warp owns one d-plane per dgroup iteration;
// smem acc[d][20]: within a warp d is fixed -> 19 distinct banks, only
// same-label lanes serialize.
__global__ __launch_bounds__(256) void k_pass1(const float4* __restrict__ X,
                                               const int4* __restrict__ T) {
    __shared__ float acc[ND*20];   // 20480 B
    const int tid  = threadIdx.x;
    const int lane = tid & 31;
    const int w    = tid >> 5;
    const int b    = blockIdx.x >> 5;          // 32 tiles per batch
    const int tib  = blockIdx.x & 31;
    const int pxb  = tib * P1TILE;

    for (int i = tid; i < ND*20; i += 256) acc[i] = 0.f;

    // pack this lane's 16 pixel labels (4 per float4-iteration) into 4 regs
    unsigned lab[4];
    const int4* labs = T + ((size_t)b*HW + pxb) / 4;
    #pragma unroll
    for (int i = 0; i < 4; i++) {
        int4 l = labs[i*32 + lane];
        lab[i] = (unsigned)l.x | ((unsigned)l.y << 8) |
                 ((unsigned)l.z << 16) | ((unsigned)l.w << 24);
    }
    __syncthreads();

    const float4* base = X + (size_t)b*ND*(HW/4) + pxb/4;
    #pragma unroll 1
    for (int dg = 0; dg < 32; dg++) {
        const int d = dg*8 + w;
        const float4* plane = base + (size_t)d*(HW/4);
        float* accd = acc + d*20;
        #pragma unroll
        for (int i = 0; i < 4; i++) {
            float4 v = plane[i*32 + lane];
            unsigned L = lab[i];
            atomicAdd(accd + (L & 0xFFu),        v.x);
            atomicAdd(accd + ((L >> 8) & 0xFFu), v.y);
            atomicAdd(accd + ((L >> 16) & 0xFFu),v.z);
            atomicAdd(accd + (L >> 24),          v.w);
        }
    }
    __syncthreads();
    for (int i = tid; i < ND*20; i += 256) {
        const int d = i / 20, c = i - d*20;
        if (c < NC) atomicAdd(&g_S[c*ND + d], acc[i]);
    }
}

// ---------------- kernel 2: centers, norms, diff_loss (warp-parallel) ----------------
__global__ __launch_bounds__(256) void k_centers() {
    __shared__ float cen[NC][ND+1];
    __shared__ float cnt_s[NC];
    __shared__ float ncen_s[NC];
    __shared__ float per_i[NC];
    const int tid  = threadIdx.x;   // tid == d index
    const int lane = tid & 31;
    const int w    = tid >> 5;

    if (tid < NC) { cnt_s[tid] = g_counts[tid]; per_i[tid] = 0.f; }
    __syncthreads();
    #pragma unroll 1
    for (int c = 0; c < NC; c++) {
        float v = g_S[c*ND + tid] / fmaxf(cnt_s[c], 1.f);
        cen[c][tid] = v;
        g_centers[c*ND + tid] = v;
    }
    __syncthreads();

    // norms: warp per class, shuffle reduce
    for (int c = w; c < NC; c += 8) {
        float s = 0.f;
        #pragma unroll
        for (int dd = lane; dd < ND; dd += 32) { float v = cen[c][dd]; s += v*v; }
        #pragma unroll
        for (int o = 16; o; o >>= 1) s += __shfl_xor_sync(0xFFFFFFFFu, s, o);
        if (lane == 0) ncen_s[c] = sqrtf(s);
    }
    __syncthreads();
    if (tid < NC) g_ncen[tid] = ncen_s[tid];

    // pair matrix: warp per pair, shuffle reduce
    for (int p = w; p < NC*NC; p += 8) {
        const int i = p / NC, j = p - i*NC;
        float dot = 0.f;
        #pragma unroll
        for (int dd = lane; dd < ND; dd += 32) dot += cen[i][dd] * cen[j][dd];
        #pragma unroll
        for (int o = 16; o; o >>= 1) dot += __shfl_xor_sync(0xFFFFFFFFu, dot, o);
        if (lane == 0) {
            float s = dot / fmaxf(ncen_s[i]*ncen_s[j], EPS);
            float val = (i == j) ? (1.f - s) : fmaxf(s, 0.f);
            atomicAdd(&per_i[i], val);
        }
    }
    __syncthreads();
    if (tid == 0) {
        float dl = 0.f;
        for (int i = 0; i < NC; i++)
            if (cnt_s[i] > 0.f) dl += per_i[i] / (float)NC;
        g_diff = dl;
    }
}

// ---------------- kernel 3: per-pixel partial dot & normsq over a D-chunk ----------------
// 128 threads, 512-pixel tiles, 4 D-chunks -> 1024 blocks
__global__ __launch_bounds__(128) void k_pass2(const float4* __restrict__ X,
                                               const int4* __restrict__ T) {
    __shared__ float csh[NC*65];   // padded, conflict-free
    const int tid   = threadIdx.x;
    const int chunk = blockIdx.x & (NCHUNK-1);
    const int tile  = blockIdx.x >> 2;           // 0..255
    const int b     = tile >> 5;                 // 32 tiles per batch
    const int px0   = ((tile & 31) << 9) + (tid << 2);

    for (int i = tid; i < NC*DCH; i += 128) {
        int c = i / DCH, dd = i - c*DCH;
        csh[c*65 + dd] = g_centers[c*ND + chunk*DCH + dd];
    }
    __syncthreads();

    int4 l = T[((size_t)b*HW + px0) >> 2];
    const int la = l.x*65, lb = l.y*65, lc = l.z*65, ld = l.w*65;
    const float4* base = X + (size_t)(b*ND + chunk*DCH)*(HW/4) + (px0 >> 2);

    float dx=0,dy=0,dz=0,dw=0, nx=0,ny=0,nz=0,nw=0;
    #pragma unroll 4
    for (int dd = 0; dd < DCH; dd++) {
        float4 v = base[(size_t)dd * (HW/4)];
        dx += v.x * csh[la+dd];  nx += v.x*v.x;
        dy += v.y * csh[lb+dd];  ny += v.y*v.y;
        dz += v.z * csh[lc+dd];  nz += v.z*v.z;
        dw += v.w * csh[ld+dd];  nw += v.w*v.w;
    }
    const int n = tile*P2TILE + (tid << 2);
    *(float4*)&g_dotp[chunk*NPIX + n] = make_float4(dx,dy,dz,dw);
    *(float4*)&g_nsqp[chunk*NPIX + n] = make_float4(nx,ny,nz,nw);
}

// ---------------- kernel 4: per-pixel cos -> per-class (1-cos) sums ----------------
__global__ __launch_bounds__(256) void k_finalpix(const int* __restrict__ T) {
    __shared__ float bins[20];
    __shared__ float ncs[NC];
    const int tid = threadIdx.x;
    if (tid < 20) bins[tid] = 0.f;
    if (tid < NC) ncs[tid] = g_ncen[tid];
    __syncthreads();

    const int n = blockIdx.x*256 + tid;
    const int lab = T[n];
    float dot = 0.f, nsq = 0.f;
    #pragma unroll
    for (int c2 = 0; c2 < NCHUNK; c2++) {
        dot += g_dotp[c2*NPIX + n];
        nsq += g_nsqp[c2*NPIX + n];
    }
    float cosv = dot / fmaxf(sqrtf(nsq) * ncs[lab], EPS);
    atomicAdd(&bins[lab], 1.f - cosv);
    __syncthreads();
    if (tid < NC) atomicAdd(&g_percls[tid], bins[tid]);
}

// ---------------- kernel 5: finalize ----------------
__global__ void k_final(float* __restrict__ out) {
    float r = g_diff;
    for (int c = 0; c < NC; c++) {
        float cnt = g_counts[c];
        if (cnt > 0.f) r += g_percls[c] / fmaxf(cnt, 1.f);
    }
    out[0] = r;
}

extern "C" void kernel_launch(void* const* d_in, const int* in_sizes, int n_in,
                              void* d_out, int out_size) {
    const float4* X = (const float4*)d_in[0];   // (8,256,128,128) fp32
    const int4*   T = (const int4*)d_in[1];     // (8,128,128) int32
    float* out = (float*)d_out;

    k_zero<<<(NC*ND + 255)/256, 256>>>();
    k_count<<<32, 256>>>(T);
    k_pass1<<<NB*32, 256>>>(X, T);
    k_centers<<<1, 256>>>();
    k_pass2<<<(NPIX/P2TILE)*NCHUNK, 128>>>(X, T);
    k_finalpix<<<NPIX/256, 256>>>((const int*)d_in[1]);
    k_final<<<1, 1>>>(out);
}

// round 5
// speedup vs baseline: 1.6653x; 1.6653x over previous
#include <cuda_runtime.h>
#include <math.h>

#define NC 19
#define ND 256
#define NB 8
#define HW 16384              // 128*128
#define NPIX (NB*HW)          // 131072
#define NCHUNK 4
#define DCH (ND/NCHUNK)       // 64
#define EPS 1e-8f
#define P1 256                // pixels per pass1 block
#define NSTG 16               // d-planes staged per iteration
#define P2TILE 512

// ---------------- static scratch ----------------
__device__ float g_S[NC*ND];
__device__ float g_counts[NC];
__device__ float g_centers[NC*ND];
__device__ float g_ncen[NC];
__device__ float g_dotp[NCHUNK*NPIX];
__device__ float g_nsqp[NCHUNK*NPIX];
__device__ float g_percls[NC];
__device__ float g_diff;

// ---------------- kernel 0: zero ----------------
__global__ void k_zero() {
    int i = blockIdx.x * blockDim.x + threadIdx.x;
    if (i < NC*ND) g_S[i] = 0.f;
    if (i < NC) { g_counts[i] = 0.f; g_percls[i] = 0.f; }
}

// ---------------- kernel 1: class sums via per-tile counting sort ----------------
// block = (b, 256-pixel tile); sort labels once; per 16-plane stage, tasks
// (plane, class) do contiguous serial sums -> ONE global atomic per task.
__global__ __launch_bounds__(256) void k_pass1(const float4* __restrict__ X,
                                               const int* __restrict__ T) {
    __shared__ float vals[NSTG][P1];        // 16 KB
    __shared__ unsigned short sidx[P1];     // sorted pixel index
    __shared__ int shist[NC];               // per-class count in tile
    __shared__ int sstart[NC];              // class start offset (sorted)
    __shared__ int scur[NC];                // scatter cursor
    const int t = threadIdx.x;
    const int b    = blockIdx.x >> 6;       // 64 tiles per batch
    const int tile = blockIdx.x & 63;
    const int px0  = tile * P1;

    if (t < NC) shist[t] = 0;
    __syncthreads();
    const int lab = T[b*HW + px0 + t];
    atomicAdd(&shist[lab], 1);
    __syncthreads();
    if (t == 0) {
        int run = 0;
        #pragma unroll
        for (int c = 0; c < NC; c++) { sstart[c] = run; scur[c] = run; run += shist[c]; }
    }
    if (t < NC && shist[t] > 0) atomicAdd(&g_counts[t], (float)shist[t]);
    __syncthreads();
    {
        int pos = atomicAdd(&scur[lab], 1);
        sidx[pos] = (unsigned short)t;
    }
    __syncthreads();

    const float4* base = X + ((size_t)b*ND*HW + px0) / 4;   // +d*4096 per plane
    const int f4 = t & 63;
    const int pg = t >> 6;                                   // 0..3

    #pragma unroll 1
    for (int stage = 0; stage < ND/NSTG; stage++) {
        const int d0 = stage * NSTG;
        #pragma unroll
        for (int j = 0; j < 4; j++) {
            const int pl = j*4 + pg;
            ((float4*)&vals[pl][0])[f4] = base[(size_t)(d0 + pl) * (HW/4) + f4];
        }
        __syncthreads();
        for (int task = t; task < NSTG*NC; task += 256) {
            const int pl = task / NC;
            const int c  = task - pl*NC;
            const int s = sstart[c];
            const int e = s + shist[c];
            float sum = 0.f;
            for (int k = s; k < e; k++) sum += vals[pl][sidx[k]];
            if (e > s) atomicAdd(&g_S[c*ND + d0 + pl], sum);
        }
        __syncthreads();
    }
}

// ---------------- kernel 2: centers, norms, diff_loss ----------------
__global__ __launch_bounds__(256) void k_centers() {
    __shared__ float cen[NC][ND+1];
    __shared__ float cnt_s[NC];
    __shared__ float ncen_s[NC];
    __shared__ float per_i[NC];
    const int tid  = threadIdx.x;   // == d index
    const int lane = tid & 31;
    const int w    = tid >> 5;

    if (tid < NC) { cnt_s[tid] = g_counts[tid]; per_i[tid] = 0.f; }
    __syncthreads();
    #pragma unroll
    for (int c = 0; c < NC; c++) {       // unrolled: 19 independent LDGs
        float v = g_S[c*ND + tid] / fmaxf(cnt_s[c], 1.f);
        cen[c][tid] = v;
        g_centers[c*ND + tid] = v;
    }
    __syncthreads();

    for (int c = w; c < NC; c += 8) {
        float s = 0.f;
        #pragma unroll
        for (int dd = lane; dd < ND; dd += 32) { float v = cen[c][dd]; s += v*v; }
        #pragma unroll
        for (int o = 16; o; o >>= 1) s += __shfl_xor_sync(0xFFFFFFFFu, s, o);
        if (lane == 0) ncen_s[c] = sqrtf(s);
    }
    __syncthreads();
    if (tid < NC) g_ncen[tid] = ncen_s[tid];

    // thread per (i,j) pair, serial 256-FMA dot from smem
    for (int p = tid; p < NC*NC; p += 256) {
        const int i = p / NC, j = p - i*NC;
        float dot = 0.f;
        #pragma unroll 8
        for (int dd = 0; dd < ND; dd++) dot += cen[i][dd] * cen[j][dd];
        float s = dot / fmaxf(ncen_s[i]*ncen_s[j], EPS);
        float val = (i == j) ? (1.f - s) : fmaxf(s, 0.f);
        atomicAdd(&per_i[i], val);
    }
    __syncthreads();
    if (tid == 0) {
        float dl = 0.f;
        for (int i = 0; i < NC; i++)
            if (cnt_s[i] > 0.f) dl += per_i[i] / (float)NC;
        g_diff = dl;
    }
}

// ---------------- kernel 3: per-pixel partial dot & normsq over a D-chunk ----------------
__global__ __launch_bounds__(128) void k_pass2(const float4* __restrict__ X,
                                               const int4* __restrict__ T) {
    __shared__ float csh[NC*65];
    const int tid   = threadIdx.x;
    const int chunk = blockIdx.x & (NCHUNK-1);
    const int tile  = blockIdx.x >> 2;
    const int b     = tile >> 5;
    const int px0   = ((tile & 31) << 9) + (tid << 2);

    for (int i = tid; i < NC*DCH; i += 128) {
        int c = i / DCH, dd = i - c*DCH;
        csh[c*65 + dd] = g_centers[c*ND + chunk*DCH + dd];
    }
    __syncthreads();

    int4 l = T[((size_t)b*HW + px0) >> 2];
    const int la = l.x*65, lb = l.y*65, lc = l.z*65, ld = l.w*65;
    const float4* base = X + (size_t)(b*ND + chunk*DCH)*(HW/4) + (px0 >> 2);

    float dx=0,dy=0,dz=0,dw=0, nx=0,ny=0,nz=0,nw=0;
    #pragma unroll 4
    for (int dd = 0; dd < DCH; dd++) {
        float4 v = base[(size_t)dd * (HW/4)];
        dx += v.x * csh[la+dd];  nx += v.x*v.x;
        dy += v.y * csh[lb+dd];  ny += v.y*v.y;
        dz += v.z * csh[lc+dd];  nz += v.z*v.z;
        dw += v.w * csh[ld+dd];  nw += v.w*v.w;
    }
    const int n = tile*P2TILE + (tid << 2);
    *(float4*)&g_dotp[chunk*NPIX + n] = make_float4(dx,dy,dz,dw);
    *(float4*)&g_nsqp[chunk*NPIX + n] = make_float4(nx,ny,nz,nw);
}

// ---------------- kernel 4: per-pixel cos -> per-class (1-cos) sums ----------------
__global__ __launch_bounds__(256) void k_finalpix(const int* __restrict__ T) {
    __shared__ float bins[20];
    __shared__ float ncs[NC];
    const int tid = threadIdx.x;
    if (tid < 20) bins[tid] = 0.f;
    if (tid < NC) ncs[tid] = g_ncen[tid];
    __syncthreads();

    const int n = blockIdx.x*256 + tid;
    const int lab = T[n];
    float dot = 0.f, nsq = 0.f;
    #pragma unroll
    for (int c2 = 0; c2 < NCHUNK; c2++) {
        dot += g_dotp[c2*NPIX + n];
        nsq += g_nsqp[c2*NPIX + n];
    }
    float cosv = dot / fmaxf(sqrtf(nsq) * ncs[lab], EPS);
    atomicAdd(&bins[lab], 1.f - cosv);
    __syncthreads();
    if (tid < NC) atomicAdd(&g_percls[tid], bins[tid]);
}

// ---------------- kernel 5: finalize ----------------
__global__ void k_final(float* __restrict__ out) {
    float r = g_diff;
    for (int c = 0; c < NC; c++) {
        float cnt = g_counts[c];
        if (cnt > 0.f) r += g_percls[c] / fmaxf(cnt, 1.f);
    }
    out[0] = r;
}

extern "C" void kernel_launch(void* const* d_in, const int* in_sizes, int n_in,
                              void* d_out, int out_size) {
    const float4* X = (const float4*)d_in[0];   // (8,256,128,128) fp32
    const int4*   T4 = (const int4*)d_in[1];    // (8,128,128) int32
    const int*    T  = (const int*)d_in[1];
    float* out = (float*)d_out;

    k_zero<<<(NC*ND + 255)/256, 256>>>();
    k_pass1<<<NB*64, 256>>>(X, T);
    k_centers<<<1, 256>>>();
    k_pass2<<<(NPIX/P2TILE)*NCHUNK, 128>>>(X, T4);
    k_finalpix<<<NPIX/256, 256>>>(T);
    k_final<<<1, 1>>>(out);
}

// round 8
// speedup vs baseline: 3.4181x; 2.0525x over previous
#include <cuda_runtime.h>
#include <math.h>

#define NC 19
#define ND 256
#define NB 8
#define HW 16384              // 128*128
#define NPIX (NB*HW)          // 131072
#define NCHUNK 8
#define DCH (ND/NCHUNK)       // 32
#define EPS 1e-8f
#define P2TILE 512

// ---------------- static scratch ----------------
__device__ float g_S[NC*ND];
__device__ float g_counts[NC];
__device__ float g_centers[NC*ND];
__device__ float g_ncen[NC];
__device__ unsigned char g_lab8[NPIX];
__device__ float g_dotp[NCHUNK*NPIX];   // 4 MB
__device__ float g_nsqp[NCHUNK*NPIX];   // 4 MB
__device__ float g_percls[NC];
__device__ float g_diff;

// ---------------- kernel 0a: zero g_counts (must precede k_prep) ----------------
__global__ void k_zero_counts() { if (threadIdx.x < NC) g_counts[threadIdx.x] = 0.f; }

// ---------------- kernel 0b: prep — zero accum, pack labels, histogram ----------------
// 128 blocks x 256 threads; thread handles one int4 (4 labels)
__global__ __launch_bounds__(256) void k_prep(const int4* __restrict__ T) {
    __shared__ int h[NC];
    const int t = threadIdx.x;
    if (t < NC) h[t] = 0;
    __syncthreads();
    const int i = blockIdx.x * 256 + t;          // 32768 int4s total
    int4 l = T[i];
    ((uchar4*)g_lab8)[i] = make_uchar4((unsigned char)l.x, (unsigned char)l.y,
                                       (unsigned char)l.z, (unsigned char)l.w);
    atomicAdd(&h[l.x], 1); atomicAdd(&h[l.y], 1);
    atomicAdd(&h[l.z], 1); atomicAdd(&h[l.w], 1);
    if (blockIdx.x == 0) {                       // zero g_S / g_percls (read only by later launches)
        for (int k = t; k < NC*ND; k += 256) g_S[k] = 0.f;
        if (t < NC) g_percls[t] = 0.f;
    }
    __syncthreads();
    if (t < NC) atomicAdd(&g_counts[t], (float)h[t]);
}

// ---------------- kernel 1: class sums, lane-private smem bins ----------------
// block = (b, d-plane); sbin[warp][class][lane] -> every access hits bank==lane,
// plain LDS/FADD/STS, zero conflicts, zero atomics in the hot loop.
__global__ __launch_bounds__(256) void k_pass1(const float4* __restrict__ X) {
    __shared__ float sbin[8*NC*32];       // 19456 B
    __shared__ float red[8*NC];
    const int t    = threadIdx.x;
    const int lane = t & 31;
    const int w    = t >> 5;
    const int b    = blockIdx.x >> 8;
    const int d    = blockIdx.x & 255;

    for (int i = t; i < 8*NC*32; i += 256) sbin[i] = 0.f;
    __syncthreads();

    const float4* plane = X + (size_t)(b*ND + d) * (HW/4);
    const uchar4* labs  = (const uchar4*)g_lab8 + (size_t)b * (HW/4);
    float* mybin = sbin + w*(NC*32) + lane;   // + c*32 selects class

    #pragma unroll 4
    for (int k = 0; k < 16; k++) {
        float4 v = plane[k*256 + t];
        uchar4 L = labs[k*256 + t];
        mybin[(int)L.x * 32] += v.x;
        mybin[(int)L.y * 32] += v.y;
        mybin[(int)L.z * 32] += v.z;
        mybin[(int)L.w * 32] += v.w;
    }
    __syncthreads();

    // reduce 32 lanes of each (warp,class) copy; lane-rotated to avoid conflicts
    if (t < 8*NC) {
        const float* row = sbin + t*32;
        float s = 0.f;
        #pragma unroll
        for (int k = 0; k < 32; k++) s += row[(k + t) & 31];
        red[t] = s;
    }
    __syncthreads();
    if (t < NC) {
        float s = 0.f;
        #pragma unroll
        for (int ww = 0; ww < 8; ww++) s += red[ww*NC + t];
        atomicAdd(&g_S[t*ND + d], s);
    }
}

// ---------------- kernel 2: centers, norms, diff_loss ----------------
__global__ __launch_bounds__(256) void k_centers() {
    __shared__ float cen[NC][ND+1];
    __shared__ float cnt_s[NC];
    __shared__ float ncen_s[NC];
    __shared__ float per_i[NC];
    const int tid  = threadIdx.x;   // == d index
    const int lane = tid & 31;
    const int w    = tid >> 5;

    if (tid < NC) { cnt_s[tid] = g_counts[tid]; per_i[tid] = 0.f; }
    __syncthreads();
    #pragma unroll
    for (int c = 0; c < NC; c++) {       // unrolled: 19 independent LDGs
        float v = g_S[c*ND + tid] / fmaxf(cnt_s[c], 1.f);
        cen[c][tid] = v;
        g_centers[c*ND + tid] = v;
    }
    __syncthreads();

    for (int c = w; c < NC; c += 8) {
        float s = 0.f;
        #pragma unroll
        for (int dd = lane; dd < ND; dd += 32) { float v = cen[c][dd]; s += v*v; }
        #pragma unroll
        for (int o = 16; o; o >>= 1) s += __shfl_xor_sync(0xFFFFFFFFu, s, o);
        if (lane == 0) ncen_s[c] = sqrtf(s);
    }
    __syncthreads();
    if (tid < NC) g_ncen[tid] = ncen_s[tid];

    for (int p = tid; p < NC*NC; p += 256) {
        const int i = p / NC, j = p - i*NC;
        float dot = 0.f;
        #pragma unroll 8
        for (int dd = 0; dd < ND; dd++) dot += cen[i][dd] * cen[j][dd];
        float s = dot / fmaxf(ncen_s[i]*ncen_s[j], EPS);
        float val = (i == j) ? (1.f - s) : fmaxf(s, 0.f);
        atomicAdd(&per_i[i], val);
    }
    __syncthreads();
    if (tid == 0) {
        float dl = 0.f;
        for (int i = 0; i < NC; i++)
            if (cnt_s[i] > 0.f) dl += per_i[i] / (float)NC;
        g_diff = dl;
    }
}

// ---------------- kernel 3: per-pixel partial dot & normsq over a D-chunk ----------------
// 2048 blocks (256 tiles x 8 chunks), 128 threads, thread owns 4 pixels
__global__ __launch_bounds__(128) void k_pass2(const float4* __restrict__ X,
                                               const int4* __restrict__ T) {
    __shared__ float csh[NC*33];   // [class][dd] padded
    const int tid   = threadIdx.x;
    const int chunk = blockIdx.x & (NCHUNK-1);
    const int tile  = blockIdx.x >> 3;           // 0..255
    const int b     = tile >> 5;                 // 32 tiles per batch
    const int px0   = ((tile & 31) << 9) + (tid << 2);

    for (int i = tid; i < NC*DCH; i += 128) {
        int c = i / DCH, dd = i - c*DCH;
        csh[c*33 + dd] = g_centers[c*ND + chunk*DCH + dd];
    }
    __syncthreads();

    int4 l = T[((size_t)b*HW + px0) >> 2];
    const int la = l.x*33, lb = l.y*33, lc = l.z*33, ld = l.w*33;
    const float4* base = X + (size_t)(b*ND + chunk*DCH)*(HW/4) + (px0 >> 2);

    float dx=0,dy=0,dz=0,dw=0, nx=0,ny=0,nz=0,nw=0;
    #pragma unroll 8
    for (int dd = 0; dd < DCH; dd++) {
        float4 v = base[(size_t)dd * (HW/4)];
        dx += v.x * csh[la+dd];  nx += v.x*v.x;
        dy += v.y * csh[lb+dd];  ny += v.y*v.y;
        dz += v.z * csh[lc+dd];  nz += v.z*v.z;
        dw += v.w * csh[ld+dd];  nw += v.w*v.w;
    }
    const int n = tile*P2TILE + (tid << 2);
    *(float4*)&g_dotp[chunk*NPIX + n] = make_float4(dx,dy,dz,dw);
    *(float4*)&g_nsqp[chunk*NPIX + n] = make_float4(nx,ny,nz,nw);
}

// ---------------- kernel 4: per-pixel cos -> per-class (1-cos) sums ----------------
__global__ __launch_bounds__(256) void k_finalpix(const int* __restrict__ T) {
    __shared__ float bins[20];
    __shared__ float ncs[NC];
    const int tid = threadIdx.x;
    if (tid < 20) bins[tid] = 0.f;
    if (tid < NC) ncs[tid] = g_ncen[tid];
    __syncthreads();

    const int n = blockIdx.x*256 + tid;
    const int lab = T[n];
    float dot = 0.f, nsq = 0.f;
    #pragma unroll
    for (int c2 = 0; c2 < NCHUNK; c2++) {
        dot += g_dotp[c2*NPIX + n];
        nsq += g_nsqp[c2*NPIX + n];
    }
    float cosv = dot / fmaxf(sqrtf(nsq) * ncs[lab], EPS);
    atomicAdd(&bins[lab], 1.f - cosv);
    __syncthreads();
    if (tid < NC) atomicAdd(&g_percls[tid], bins[tid]);
}

// ---------------- kernel 5: finalize ----------------
__global__ void k_final(float* __restrict__ out) {
    float r = g_diff;
    for (int c = 0; c < NC; c++) {
        float cnt = g_counts[c];
        if (cnt > 0.f) r += g_percls[c] / fmaxf(cnt, 1.f);
    }
    out[0] = r;
}

extern "C" void kernel_launch(void* const* d_in, const int* in_sizes, int n_in,
                              void* d_out, int out_size) {
    const float4* X  = (const float4*)d_in[0];   // (8,256,128,128) fp32
    const int4*   T4 = (const int4*)d_in[1];     // (8,128,128) int32
    const int*    T  = (const int*)d_in[1];
    float* out = (float*)d_out;

    k_zero_counts<<<1, 32>>>();
    k_prep<<<NPIX/4/256, 256>>>(T4);
    k_pass1<<<NB*ND, 256>>>(X);
    k_centers<<<1, 256>>>();
    k_pass2<<<(NPIX/P2TILE)*NCHUNK, 128>>>(X, T4);
    k_finalpix<<<NPIX/256, 256>>>(T);
    k_final<<<1, 1>>>(out);
}

// round 9
// speedup vs baseline: 3.9984x; 1.1698x over previous
#include <cuda_runtime.h>
#include <math.h>

#define NC 19
#define ND 256
#define NB 8
#define HW 16384              // 128*128
#define NPIX (NB*HW)          // 131072
#define NCHUNK 8
#define DCH (ND/NCHUNK)       // 32
#define EPS 1e-8f
#define P2TILE 512

// ---------------- static scratch ----------------
__device__ float g_S[NC*ND];
__device__ float g_counts[NC];
__device__ float g_centers[NC*ND];
__device__ float g_ncen[NC];
__device__ unsigned char g_lab8[NPIX];
__device__ float g_dotp[NCHUNK*NPIX];   // 4 MB
__device__ float g_nsqp[NCHUNK*NPIX];   // 4 MB
__device__ float g_percls[NC];
__device__ float g_diff;

// ---------------- kernel 0a: zero g_counts / g_diff (must precede k_prep) ----------------
__global__ void k_zero_counts() {
    if (threadIdx.x < NC) g_counts[threadIdx.x] = 0.f;
    if (threadIdx.x == NC) g_diff = 0.f;
}

// ---------------- kernel 0b: prep — zero accum, pack labels, histogram ----------------
__global__ __launch_bounds__(256) void k_prep(const int4* __restrict__ T) {
    __shared__ int h[NC];
    const int t = threadIdx.x;
    if (t < NC) h[t] = 0;
    __syncthreads();
    const int i = blockIdx.x * 256 + t;          // 32768 int4s total
    int4 l = T[i];
    ((uchar4*)g_lab8)[i] = make_uchar4((unsigned char)l.x, (unsigned char)l.y,
                                       (unsigned char)l.z, (unsigned char)l.w);
    atomicAdd(&h[l.x], 1); atomicAdd(&h[l.y], 1);
    atomicAdd(&h[l.z], 1); atomicAdd(&h[l.w], 1);
    if (blockIdx.x == 0) {                       // zero g_S / g_percls (consumed by later launches)
        for (int k = t; k < NC*ND; k += 256) g_S[k] = 0.f;
        if (t < NC) g_percls[t] = 0.f;
    }
    __syncthreads();
    if (t < NC) atomicAdd(&g_counts[t], (float)h[t]);
}

// ---------------- kernel 1: class sums, lane-private smem bins ----------------
__global__ __launch_bounds__(256) void k_pass1(const float4* __restrict__ X) {
    __shared__ float sbin[8*NC*32];       // 19456 B
    __shared__ float red[8*NC];
    const int t    = threadIdx.x;
    const int lane = t & 31;
    const int w    = t >> 5;
    const int b    = blockIdx.x >> 8;
    const int d    = blockIdx.x & 255;

    for (int i = t; i < 8*NC*32; i += 256) sbin[i] = 0.f;
    __syncthreads();

    const float4* plane = X + (size_t)(b*ND + d) * (HW/4);
    const uchar4* labs  = (const uchar4*)g_lab8 + (size_t)b * (HW/4);
    float* mybin = sbin + w*(NC*32) + lane;

    #pragma unroll 4
    for (int k = 0; k < 16; k++) {
        float4 v = plane[k*256 + t];
        uchar4 L = labs[k*256 + t];
        mybin[(int)L.x * 32] += v.x;
        mybin[(int)L.y * 32] += v.y;
        mybin[(int)L.z * 32] += v.z;
        mybin[(int)L.w * 32] += v.w;
    }
    __syncthreads();

    if (t < 8*NC) {
        const float* row = sbin + t*32;
        float s = 0.f;
        #pragma unroll
        for (int k = 0; k < 32; k++) s += row[(k + t) & 31];
        red[t] = s;
    }
    __syncthreads();
    if (t < NC) {
        float s = 0.f;
        #pragma unroll
        for (int ww = 0; ww < 8; ww++) s += red[ww*NC + t];
        atomicAdd(&g_S[t*ND + d], s);
    }
}

// ---------------- kernel 2a: centers + norms, one block per class ----------------
__global__ __launch_bounds__(256) void k_centers() {
    __shared__ float red[8];
    const int c    = blockIdx.x;           // 0..18
    const int tid  = threadIdx.x;          // == d index
    const int lane = tid & 31;
    const int w    = tid >> 5;

    const float cnt = g_counts[c];
    float v = g_S[c*ND + tid] / fmaxf(cnt, 1.f);
    g_centers[c*ND + tid] = v;

    float s = v*v;
    #pragma unroll
    for (int o = 16; o; o >>= 1) s += __shfl_xor_sync(0xFFFFFFFFu, s, o);
    if (lane == 0) red[w] = s;
    __syncthreads();
    if (tid == 0) {
        float tot = red[0]+red[1]+red[2]+red[3]+red[4]+red[5]+red[6]+red[7];
        g_ncen[c] = sqrtf(tot);
    }
}

// ---------------- kernel 2b: diff_loss, one block per class i ----------------
__global__ __launch_bounds__(256) void k_diff() {
    __shared__ float ceni[ND];
    __shared__ float acc[8];
    const int i    = blockIdx.x;
    const int tid  = threadIdx.x;
    const int lane = tid & 31;
    const int w    = tid >> 5;

    ceni[tid] = g_centers[i*ND + tid];
    if (tid < 8) acc[tid] = 0.f;
    __syncthreads();

    const float ni = g_ncen[i];
    float mysum = 0.f;
    for (int j = w; j < NC; j += 8) {
        float dot = 0.f;
        #pragma unroll
        for (int dd = lane; dd < ND; dd += 32) dot += ceni[dd] * g_centers[j*ND + dd];
        #pragma unroll
        for (int o = 16; o; o >>= 1) dot += __shfl_xor_sync(0xFFFFFFFFu, dot, o);
        if (lane == 0) {
            float s = dot / fmaxf(ni * g_ncen[j], EPS);
            mysum += (i == j) ? (1.f - s) : fmaxf(s, 0.f);
        }
    }
    if (lane == 0) acc[w] = mysum;
    __syncthreads();
    if (tid == 0 && g_counts[i] > 0.f) {
        float tot = acc[0]+acc[1]+acc[2]+acc[3]+acc[4]+acc[5]+acc[6]+acc[7];
        atomicAdd(&g_diff, tot / (float)NC);
    }
}

// ---------------- kernel 3: per-pixel partial dot & normsq over a D-chunk ----------------
__global__ __launch_bounds__(128) void k_pass2(const float4* __restrict__ X,
                                               const int4* __restrict__ T) {
    __shared__ float csh[NC*33];
    const int tid   = threadIdx.x;
    const int chunk = blockIdx.x & (NCHUNK-1);
    const int tile  = blockIdx.x >> 3;           // 0..255
    const int b     = tile >> 5;
    const int px0   = ((tile & 31) << 9) + (tid << 2);

    for (int i = tid; i < NC*DCH; i += 128) {
        int c = i / DCH, dd = i - c*DCH;
        csh[c*33 + dd] = g_centers[c*ND + chunk*DCH + dd];
    }
    __syncthreads();

    int4 l = T[((size_t)b*HW + px0) >> 2];
    const int la = l.x*33, lb = l.y*33, lc = l.z*33, ld = l.w*33;
    const float4* base = X + (size_t)(b*ND + chunk*DCH)*(HW/4) + (px0 >> 2);

    float dx=0,dy=0,dz=0,dw=0, nx=0,ny=0,nz=0,nw=0;
    #pragma unroll 8
    for (int dd = 0; dd < DCH; dd++) {
        float4 v = base[(size_t)dd * (HW/4)];
        dx += v.x * csh[la+dd];  nx += v.x*v.x;
        dy += v.y * csh[lb+dd];  ny += v.y*v.y;
        dz += v.z * csh[lc+dd];  nz += v.z*v.z;
        dw += v.w * csh[ld+dd];  nw += v.w*v.w;
    }
    const int n = tile*P2TILE + (tid << 2);
    *(float4*)&g_dotp[chunk*NPIX + n] = make_float4(dx,dy,dz,dw);
    *(float4*)&g_nsqp[chunk*NPIX + n] = make_float4(nx,ny,nz,nw);
}

// ---------------- kernel 4: per-pixel cos -> per-class (1-cos) sums ----------------
__global__ __launch_bounds__(256) void k_finalpix(const int* __restrict__ T) {
    __shared__ float bins[20];
    __shared__ float ncs[NC];
    const int tid = threadIdx.x;
    if (tid < 20) bins[tid] = 0.f;
    if (tid < NC) ncs[tid] = g_ncen[tid];
    __syncthreads();

    const int n = blockIdx.x*256 + tid;
    const int lab = T[n];
    float dot = 0.f, nsq = 0.f;
    #pragma unroll
    for (int c2 = 0; c2 < NCHUNK; c2++) {
        dot += g_dotp[c2*NPIX + n];
        nsq += g_nsqp[c2*NPIX + n];
    }
    float cosv = dot / fmaxf(sqrtf(nsq) * ncs[lab], EPS);
    atomicAdd(&bins[lab], 1.f - cosv);
    __syncthreads();
    if (tid < NC) atomicAdd(&g_percls[tid], bins[tid]);
}

// ---------------- kernel 5: finalize ----------------
__global__ void k_final(float* __restrict__ out) {
    float r = g_diff;
    for (int c = 0; c < NC; c++) {
        float cnt = g_counts[c];
        if (cnt > 0.f) r += g_percls[c] / fmaxf(cnt, 1.f);
    }
    out[0] = r;
}

extern "C" void kernel_launch(void* const* d_in, const int* in_sizes, int n_in,
                              void* d_out, int out_size) {
    const float4* X  = (const float4*)d_in[0];   // (8,256,128,128) fp32
    const int4*   T4 = (const int4*)d_in[1];     // (8,128,128) int32
    const int*    T  = (const int*)d_in[1];
    float* out = (float*)d_out;

    k_zero_counts<<<1, 32>>>();
    k_prep<<<NPIX/4/256, 256>>>(T4);
    k_pass1<<<NB*ND, 256>>>(X);
    k_centers<<<NC, 256>>>();
    k_diff<<<NC, 256>>>();
    k_pass2<<<(NPIX/P2TILE)*NCHUNK, 128>>>(X, T4);
    k_finalpix<<<NPIX/256, 256>>>(T);
    k_final<<<1, 1>>>(out);
}